// round 14
// baseline (speedup 1.0000x reference)
#include <cuda_runtime.h>
#include <cuda_bf16.h>
#include <cuda_fp16.h>
#include <cstdint>
#include <cstddef>

// Problem constants
#define Bq 8
#define Nq 4096
#define Pq 4096
#define Kq 32
#define Cq 128
#define Wq 16
#define EPSq 1e-5f

#define TPT 16                        // points per gather block
#define GBLK_PER_B (Pq / TPT)         // 256
#define NPTILE (Pq / 128)             // 32 p-tiles per batch
#define NBLK2 (Bq * NPTILE)           // 256 stat rows
#define CONV_BLKS 4096                // convert blocks in merged prep kernel
#define GEMM_BLKS (NPTILE * 2 * Bq)   // 512

// ------------------- device globals (no allocation allowed) -------------------
__device__ __align__(256) __half g_Ph[(size_t)Bq * Nq * Cq];     // fp16 points
__device__ __align__(256) __half g_S[(size_t)Bq * Pq * 512];     // fp16 S, [s][p][i]
__device__ __align__(256) __half g_Ahf[128 * 512];               // A' fp16, [j][i]
__device__ __align__(256) __half g_Yth[(size_t)Bq * Cq * Pq];    // fp16 Y, [s][j][p]
__device__ float g_ps[NBLK2 * Cq];
__device__ float g_pq[NBLK2 * Cq];
__device__ float g_scale[Cq];
__device__ float g_shift[Cq];
__device__ int   g_cnt[Bq];
__device__ unsigned g_ctr;            // gemm completion ticket (reset by prepconv)

// ------------------- helpers -------------------
__device__ __forceinline__ unsigned long long pk2(float x, float y) {
    unsigned long long r;
    asm("mov.b64 %0, {%1,%2};" : "=l"(r) : "f"(x), "f"(y));
    return r;
}
__device__ __forceinline__ void fma2(unsigned long long& d,
                                     unsigned long long a,
                                     unsigned long long b) {
    asm("fma.rn.f32x2 %0, %1, %2, %0;" : "+l"(d) : "l"(a), "l"(b));
}
__device__ __forceinline__ float2 up2(unsigned long long v) {
    float x, y;
    asm("mov.b64 {%0,%1}, %2;" : "=f"(x), "=f"(y) : "l"(v));
    return make_float2(x, y);
}
__device__ __forceinline__ uint32_t smem_to_u32(const void* p) {
    uint32_t a;
    asm("{ .reg .u64 t; cvta.to.shared.u64 t, %1; cvt.u32.u64 %0, t; }"
        : "=r"(a) : "l"(p));
    return a;
}
__device__ __forceinline__ __half2 h2_from_u32(uint32_t u) {
    __half2 h;
    *reinterpret_cast<uint32_t*>(&h) = u;
    return h;
}

#define CP_ASYNC16(dst, src) \
    asm volatile("cp.async.cg.shared.global [%0], [%1], 16;" \
                 :: "r"(dst), "l"(src) : "memory")
#define CP_COMMIT() asm volatile("cp.async.commit_group;" ::: "memory")
#define CP_WAIT(n)  asm volatile("cp.async.wait_group %0;" :: "n"(n) : "memory")

__device__ __forceinline__ void ldsm_x4(uint32_t addr, uint32_t* r) {
    asm volatile("ldmatrix.sync.aligned.m8n8.x4.shared.b16 {%0,%1,%2,%3}, [%4];"
                 : "=r"(r[0]), "=r"(r[1]), "=r"(r[2]), "=r"(r[3]) : "r"(addr));
}
__device__ __forceinline__ void mma_f16(float* c, const uint32_t* a,
                                        uint32_t b0, uint32_t b1) {
    asm volatile(
        "mma.sync.aligned.m16n8k16.row.col.f32.f16.f16.f32 "
        "{%0,%1,%2,%3}, {%4,%5,%6,%7}, {%8,%9}, {%0,%1,%2,%3};"
        : "+f"(c[0]), "+f"(c[1]), "+f"(c[2]), "+f"(c[3])
        : "r"(a[0]), "r"(a[1]), "r"(a[2]), "r"(a[3]), "r"(b0), "r"(b1));
}
__device__ __forceinline__ float ldg_cg(const float* p) {
    float v;
    asm volatile("ld.global.cg.f32 %0, [%1];" : "=f"(v) : "l"(p));
    return v;
}

// ============================================================
// prepconv: merged kernel.
//   blocks [0, CONV_BLKS): points fp32 -> fp16 (skip unused batches)
//   blocks [CONV_BLKS, CONV_BLKS+256): A' fp16 [j][i] + batch counts
//   also resets the gemm completion ticket.
//   NOTE: bl dropped — per-channel constants cancel in the LayerNorm.
// ============================================================
__global__ __launch_bounds__(256) void prepconv_kernel(
    const float* __restrict__ points,
    const float* __restrict__ Ww,
    const float* __restrict__ bw,
    const float* __restrict__ Wl,
    const int* __restrict__ didx) {
    const int blk = blockIdx.x;
    if (blk == 0 && threadIdx.x == 0) g_ctr = 0u;
    if (blk < CONV_BLKS) {
        const int s = blk >> 9;                  // 512 blocks per batch
        bool used = false;
#pragma unroll
        for (int b = 0; b < Bq; b++) used |= (didx[b] == s);
        if (!used) return;
        size_t idx = ((size_t)blk * 256 + threadIdx.x) * 4;
        float4 v = *reinterpret_cast<const float4*>(points + idx);
        *reinterpret_cast<__half2*>(g_Ph + idx) = __floats2half2_rn(v.x, v.y);
        *reinterpret_cast<__half2*>(g_Ph + idx + 2) = __floats2half2_rn(v.z, v.w);
        return;
    }
    if (blk == CONV_BLKS && threadIdx.x < Bq) {
        int c = 0;
#pragma unroll
        for (int b = 0; b < Bq; b++) c += (didx[b] == (int)threadIdx.x);
        g_cnt[threadIdx.x] = c;
    }
    int idx = (blk - CONV_BLKS) * 256 + threadIdx.x;   // 0 .. 65535
    int d = idx >> 14;
    int c = (idx >> 7) & (Cq - 1);
    int j = idx & (Cq - 1);
    float acc = 0.f;
#pragma unroll
    for (int w = 0; w < Wq; w++) {
        float coef = (d < 3) ? Ww[d * Wq + w] : bw[w];
        acc = fmaf(coef, Wl[(c * Wq + w) * Cq + j], acc);
    }
    int i = (d << 7) | c;
    g_Ahf[(size_t)j * 512 + i] = __float2half_rn(acc);
}

// ============================================================
// gather: S[p,i] = sum_k coef[k,d] * points_h[s, nbr[k], c]; emit fp16
//   thread handles 4 channels (c4) x 4 points via LDG.64
// ============================================================
__global__ __launch_bounds__(128, 8) void gather_kernel(
    const float* __restrict__ lc,
    const int* __restrict__ nbr) {
    __shared__ ulonglong2 s_L[TPT][Kq];
    __shared__ uint32_t s_off[TPT][Kq];

    const int tid = threadIdx.x;
    const int s = blockIdx.y;
    if (g_cnt[s] == 0) return;
    const int p0 = blockIdx.x * TPT;
    const size_t base = ((size_t)s * Pq + p0) * Kq;

    for (int i = tid; i < TPT * Kq; i += 128) {
        int t = i >> 5, k = i & 31;
        s_off[t][k] = (uint32_t)nbr[base + (size_t)t * Kq + k] << 8;   // *256B row
        const float* Lp = lc + (base + (size_t)t * Kq + k) * 3;
        s_L[t][k] = make_ulonglong2(pk2(Lp[0], Lp[1]), pk2(Lp[2], 1.0f));
    }
    __syncthreads();

    const int c4 = tid & 31;          // channel quad: channels 4*c4 .. 4*c4+3
    const int h = tid >> 5;           // 0..3 point group
    const char* ptsb = (const char*)(g_Ph + (size_t)s * Nq * Cq) + 8 * c4;

#pragma unroll 1
    for (int tt = 0; tt < 4; tt++) {
        const int t = tt * 4 + h;
        unsigned long long a01[4], a23[4];
#pragma unroll
        for (int c = 0; c < 4; c++) { a01[c] = 0ull; a23[c] = 0ull; }
#pragma unroll
        for (int k = 0; k < Kq; k++) {
            uint2 w = *reinterpret_cast<const uint2*>(ptsb + s_off[t][k]);
            float2 v0 = __half22float2(h2_from_u32(w.x));
            float2 v1 = __half22float2(h2_from_u32(w.y));
            ulonglong2 L = s_L[t][k];
            unsigned long long p0v = pk2(v0.x, v0.x), p1v = pk2(v0.y, v0.y);
            unsigned long long p2v = pk2(v1.x, v1.x), p3v = pk2(v1.y, v1.y);
            fma2(a01[0], p0v, L.x); fma2(a23[0], p0v, L.y);
            fma2(a01[1], p1v, L.x); fma2(a23[1], p1v, L.y);
            fma2(a01[2], p2v, L.x); fma2(a23[2], p2v, L.y);
            fma2(a01[3], p3v, L.x); fma2(a23[3], p3v, L.y);
        }
        const size_t rb = ((size_t)s * Pq + p0 + t) * 512;
        float2 f01[4], f23[4];
#pragma unroll
        for (int c = 0; c < 4; c++) { f01[c] = up2(a01[c]); f23[c] = up2(a23[c]); }
        uint2 st;
        __half2 ha, hb;
        ha = __floats2half2_rn(f01[0].x, f01[1].x);
        hb = __floats2half2_rn(f01[2].x, f01[3].x);
        st.x = *reinterpret_cast<uint32_t*>(&ha);
        st.y = *reinterpret_cast<uint32_t*>(&hb);
        *reinterpret_cast<uint2*>(g_S + rb + 0 * 128 + 4 * c4) = st;
        ha = __floats2half2_rn(f01[0].y, f01[1].y);
        hb = __floats2half2_rn(f01[2].y, f01[3].y);
        st.x = *reinterpret_cast<uint32_t*>(&ha);
        st.y = *reinterpret_cast<uint32_t*>(&hb);
        *reinterpret_cast<uint2*>(g_S + rb + 1 * 128 + 4 * c4) = st;
        ha = __floats2half2_rn(f23[0].x, f23[1].x);
        hb = __floats2half2_rn(f23[2].x, f23[3].x);
        st.x = *reinterpret_cast<uint32_t*>(&ha);
        st.y = *reinterpret_cast<uint32_t*>(&hb);
        *reinterpret_cast<uint2*>(g_S + rb + 2 * 128 + 4 * c4) = st;
        ha = __floats2half2_rn(f23[0].y, f23[1].y);
        hb = __floats2half2_rn(f23[2].y, f23[3].y);
        st.x = *reinterpret_cast<uint32_t*>(&ha);
        st.y = *reinterpret_cast<uint32_t*>(&hb);
        *reinterpret_cast<uint2*>(g_S + rb + 3 * 128 + 4 * c4) = st;
    }
}

// ============================================================
// GEMM: Y[p,j] = S[p,i] * A'[j,i]^T  via mma.sync fp16
//   block tile 128p x 64j; K chunks of 64 (8 chunks); 2-stage;
//   ONE barrier per chunk; 3 CTAs/SM.
//   LN stats folded in: threadfence-reduction ticket; LAST block does the
//   full deterministic weighted reduction and writes g_scale/g_shift.
// ============================================================
#define STILE_B 18432                // 128 rows * 144B
#define ATILE_B 9216                 // 64 rows * 144B
#define OFF_S   0
#define OFF_A   (STILE_B)
#define BUF_B   (STILE_B + ATILE_B)       // 27648
#define GSM_TOTAL (2 * BUF_B)             // 55296 (epilogue 64*132*4=33792 fits)

__global__ __launch_bounds__(256, 3) void gemm_kernel(
    const float* __restrict__ gamma,
    const float* __restrict__ beta) {
    extern __shared__ __align__(128) char sm[];
    __shared__ unsigned s_last;
    const int tid = threadIdx.x;
    const int wid = tid >> 5;
    const int L = tid & 31;
    const int srcb = blockIdx.y;

    if (g_cnt[srcb] != 0) {
        const int pt = blockIdx.x >> 1;
        const int jh = blockIdx.x & 1;     // which 64-j half
        const int wm = wid >> 1;           // 0..3  (p dim, 32 each)
        const int wn = wid & 1;            // 0..1  (j dim, 32 each)

        const uint32_t smb = smem_to_u32(sm);
        const __half* Sp = g_S + ((size_t)srcb * Pq + pt * 128) * 512;
        const __half* Ah = g_Ahf + (size_t)(jh * 64) * 512;

        float acc[2][4][4];
#pragma unroll
        for (int mt = 0; mt < 2; mt++)
#pragma unroll
            for (int nt = 0; nt < 4; nt++)
#pragma unroll
                for (int q = 0; q < 4; q++) acc[mt][nt][q] = 0.f;

        const int grp = L >> 3, lr = L & 7;
        const uint32_t aRow = (uint32_t)(wm * 32 + (grp & 1) * 8 + lr) * 144
                            + (uint32_t)(grp >> 1) * 16;
        const uint32_t bRow = (uint32_t)(wn * 32 + (grp >> 1) * 8 + lr) * 144
                            + (uint32_t)(grp & 1) * 16;

#define ISSUE(kc, buf) do {                                                     \
        uint32_t bb = smb + (uint32_t)(buf) * BUF_B;                            \
        _Pragma("unroll")                                                       \
        for (int ii = 0; ii < 4; ii++) {                                        \
            int u = tid + ii * 256;                                             \
            int row = u >> 3, seg = u & 7;                                      \
            CP_ASYNC16(bb + OFF_S + (uint32_t)row * 144 + (uint32_t)seg * 16,   \
                       (const char*)(Sp + (size_t)row * 512 + (kc) * 64 + seg * 8)); \
        }                                                                       \
        _Pragma("unroll")                                                       \
        for (int ii = 0; ii < 2; ii++) {                                        \
            int u = tid + ii * 256;                                             \
            int row = u >> 3, seg = u & 7;                                      \
            CP_ASYNC16(bb + OFF_A + (uint32_t)row * 144 + (uint32_t)seg * 16,   \
                       (const char*)(Ah + (size_t)row * 512 + (kc) * 64 + seg * 8)); \
        }                                                                       \
        CP_COMMIT();                                                            \
    } while (0)

        ISSUE(0, 0);

#pragma unroll 1
        for (int kc = 0; kc < 8; kc++) {
            CP_WAIT(0);
            __syncthreads();
            if (kc < 7) ISSUE(kc + 1, (kc + 1) & 1);   // safe: readers passed sync

            const uint32_t bb = smb + (uint32_t)(kc & 1) * BUF_B;
#pragma unroll
            for (int ks = 0; ks < 4; ks++) {
                uint32_t af[2][4];
#pragma unroll
                for (int mt = 0; mt < 2; mt++) {
                    uint32_t ao = aRow + (uint32_t)mt * (16 * 144) + (uint32_t)ks * 32;
                    ldsm_x4(bb + OFF_S + ao, af[mt]);
                }
#pragma unroll
                for (int ng = 0; ng < 2; ng++) {
                    uint32_t bh[4];
                    uint32_t bo = bRow + (uint32_t)ng * (16 * 144) + (uint32_t)ks * 32;
                    ldsm_x4(bb + OFF_A + bo, bh);
#pragma unroll
                    for (int mt = 0; mt < 2; mt++) {
#pragma unroll
                        for (int t2 = 0; t2 < 2; t2++) {
                            mma_f16(acc[mt][2 * ng + t2], af[mt],
                                    bh[2 * t2], bh[2 * t2 + 1]);
                        }
                    }
                }
            }
        }
        __syncthreads();

        // ---- epilogue: C frags -> smem [64j][132] -> fp16 Y + LN partials ----
        float* yt = (float*)sm;
        {
            const int pb = wm * 32 + (L >> 2);
            const int jb = wn * 32 + ((L & 3) << 1);
#pragma unroll
            for (int mt = 0; mt < 2; mt++) {
#pragma unroll
                for (int nt = 0; nt < 4; nt++) {
                    const float* c = acc[mt][nt];
                    int p = pb + mt * 16;
                    int j = jb + nt * 8;
                    yt[j * 132 + p] = c[0];
                    yt[(j + 1) * 132 + p] = c[1];
                    yt[j * 132 + p + 8] = c[2];
                    yt[(j + 1) * 132 + p + 8] = c[3];
                }
            }
        }
        __syncthreads();

        const int blk2 = srcb * NPTILE + pt;
#pragma unroll 1
        for (int rr = 0; rr < 8; rr++) {
            int j = wid * 8 + rr;          // local j in [0,64)
            int jg = jh * 64 + j;          // global output channel
            float4 v = *reinterpret_cast<const float4*>(yt + j * 132 + L * 4);
            __half2 h0 = __floats2half2_rn(v.x, v.y);
            __half2 h1 = __floats2half2_rn(v.z, v.w);
            uint2 st;
            st.x = *reinterpret_cast<uint32_t*>(&h0);
            st.y = *reinterpret_cast<uint32_t*>(&h1);
            *reinterpret_cast<uint2*>(
                g_Yth + ((size_t)srcb * Cq + jg) * Pq + pt * 128 + L * 4) = st;
            float ls = (v.x + v.y) + (v.z + v.w);
            float lq = (v.x * v.x + v.y * v.y) + (v.z * v.z + v.w * v.w);
#pragma unroll
            for (int o = 16; o > 0; o >>= 1) {
                ls += __shfl_xor_sync(0xFFFFFFFFu, ls, o);
                lq += __shfl_xor_sync(0xFFFFFFFFu, lq, o);
            }
            if (L == 0) {
                g_ps[(size_t)blk2 * Cq + jg] = ls;
                g_pq[(size_t)blk2 * Cq + jg] = lq;
            }
        }
    }

    // ---- completion ticket; LAST block computes scale/shift ----
    __threadfence();
    __syncthreads();
    if (tid == 0) {
        unsigned t = atomicAdd(&g_ctr, 1u);
        s_last = (t == (unsigned)(GEMM_BLKS - 1)) ? 1u : 0u;
    }
    __syncthreads();
    if (s_last) {
        const int j = tid & 127;
        const int g = tid >> 7;        // 0 or 1
        float s0 = 0.f, s1 = 0.f, q0 = 0.f, q1 = 0.f;
#pragma unroll 4
        for (int i = 0; i < NBLK2 / 2; i += 2) {
            int ra = g + 2 * i;
            int rb2 = g + 2 * (i + 1);
            float wa = (float)g_cnt[ra >> 5];
            float wb = (float)g_cnt[rb2 >> 5];
            s0 += wa * ldg_cg(g_ps + (size_t)ra * Cq + j);
            q0 += wa * ldg_cg(g_pq + (size_t)ra * Cq + j);
            s1 += wb * ldg_cg(g_ps + (size_t)rb2 * Cq + j);
            q1 += wb * ldg_cg(g_pq + (size_t)rb2 * Cq + j);
        }
        float* red = (float*)sm;
        red[g * 128 + j] = s0 + s1;
        red[256 + g * 128 + j] = q0 + q1;
        __syncthreads();
        if (g == 0) {
            float S = red[j] + red[128 + j];
            float Q = red[256 + j] + red[384 + j];
            const float inv = 1.0f / (float)(Bq * Pq);
            float mean = S * inv;
            float var = Q * inv - mean * mean;
            float sc = rsqrtf(var + EPSq) * gamma[j];
            g_scale[j] = sc;
            g_shift[j] = beta[j] - mean * sc;
        }
    }
}

// ============================================================
// out: scale+shift+relu, coalesced fp16 read -> fp32 write
// ============================================================
__global__ __launch_bounds__(256) void out_kernel(float* __restrict__ out,
                                                  const int* __restrict__ didx) {
    const int b = blockIdx.x >> 7;
    const int j = blockIdx.x & 127;
    const int src = didx[b];
    const float sc = g_scale[j];
    const float sh = g_shift[j];
    const uint4* in = reinterpret_cast<const uint4*>(
        g_Yth + ((size_t)src * Cq + j) * Pq);
    float4* op = reinterpret_cast<float4*>(out + (size_t)blockIdx.x * Pq);
#pragma unroll
    for (int k = 0; k < 2; k++) {
        int idx = threadIdx.x + k * 256;      // 512 uint4 per row
        uint4 v = in[idx];
        float2 a0 = __half22float2(h2_from_u32(v.x));
        float2 a1 = __half22float2(h2_from_u32(v.y));
        float2 a2 = __half22float2(h2_from_u32(v.z));
        float2 a3 = __half22float2(h2_from_u32(v.w));
        float4 o0, o1;
        o0.x = fmaxf(fmaf(a0.x, sc, sh), 0.f);
        o0.y = fmaxf(fmaf(a0.y, sc, sh), 0.f);
        o0.z = fmaxf(fmaf(a1.x, sc, sh), 0.f);
        o0.w = fmaxf(fmaf(a1.y, sc, sh), 0.f);
        o1.x = fmaxf(fmaf(a2.x, sc, sh), 0.f);
        o1.y = fmaxf(fmaf(a2.y, sc, sh), 0.f);
        o1.z = fmaxf(fmaf(a3.x, sc, sh), 0.f);
        o1.w = fmaxf(fmaf(a3.y, sc, sh), 0.f);
        op[idx * 2] = o0;
        op[idx * 2 + 1] = o1;
    }
}

// ============================================================
// Launch
// ============================================================
extern "C" void kernel_launch(void* const* d_in, const int* in_sizes, int n_in,
                              void* d_out, int out_size) {
    const float* xyz    = (const float*)d_in[0];
    const float* points = (const float*)d_in[1];
    const float* lc     = (const float*)d_in[2];
    const int*   nbr    = (const int*)d_in[3];
    const int*   didx   = (const int*)d_in[4];
    const float* Ww     = (const float*)d_in[5];
    const float* bw     = (const float*)d_in[6];
    const float* Wl     = (const float*)d_in[7];
    const float* gamma  = (const float*)d_in[9];
    const float* beta   = (const float*)d_in[10];
    float* out = (float*)d_out;

    cudaMemcpyAsync(out, xyz, (size_t)Bq * Pq * 3 * sizeof(float),
                    cudaMemcpyDeviceToDevice, 0);

    cudaFuncSetAttribute(gemm_kernel,
                         cudaFuncAttributeMaxDynamicSharedMemorySize, GSM_TOTAL);

    prepconv_kernel<<<CONV_BLKS + 256, 256>>>(points, Ww, bw, Wl, didx);

    dim3 gg(GBLK_PER_B, Bq);
    gather_kernel<<<gg, 128>>>(lc, nbr);

    dim3 g2(NPTILE * 2, Bq);
    gemm_kernel<<<g2, 256, GSM_TOTAL>>>(gamma, beta);

    out_kernel<<<Bq * Cq, 256>>>(out + (size_t)Bq * Pq * 3, didx);
}

// round 15
// speedup vs baseline: 1.1682x; 1.1682x over previous
#include <cuda_runtime.h>
#include <cuda_bf16.h>
#include <cuda_fp16.h>
#include <cstdint>
#include <cstddef>

// Problem constants
#define Bq 8
#define Nq 4096
#define Pq 4096
#define Kq 32
#define Cq 128
#define Wq 16
#define EPSq 1e-5f

#define TPT 16                        // points per gather block
#define GBLK_PER_B (Pq / TPT)         // 256
#define NPTILE (Pq / 128)             // 32 p-tiles per batch
#define NBLK2 (Bq * NPTILE)           // 256 stat rows
#define CONV_BLKS 4096                // convert blocks in merged prep kernel

// ------------------- device globals (no allocation allowed) -------------------
__device__ __align__(256) __half g_Ph[(size_t)Bq * Nq * Cq];     // fp16 points
__device__ __align__(256) __half g_S[(size_t)Bq * Pq * 512];     // fp16 S, [s][p][i]
__device__ __align__(256) __half g_Ahf[128 * 512];               // A' fp16, [j][i]
__device__ __align__(256) __half g_Yth[(size_t)Bq * Cq * Pq];    // fp16 Y, [s][j][p]
__device__ float g_ps[NBLK2 * Cq];
__device__ float g_pq[NBLK2 * Cq];
__device__ int   g_cnt[Bq];

// ------------------- helpers -------------------
__device__ __forceinline__ unsigned long long pk2(float x, float y) {
    unsigned long long r;
    asm("mov.b64 %0, {%1,%2};" : "=l"(r) : "f"(x), "f"(y));
    return r;
}
__device__ __forceinline__ void fma2(unsigned long long& d,
                                     unsigned long long a,
                                     unsigned long long b) {
    asm("fma.rn.f32x2 %0, %1, %2, %0;" : "+l"(d) : "l"(a), "l"(b));
}
__device__ __forceinline__ float2 up2(unsigned long long v) {
    float x, y;
    asm("mov.b64 {%0,%1}, %2;" : "=f"(x), "=f"(y) : "l"(v));
    return make_float2(x, y);
}
__device__ __forceinline__ uint32_t smem_to_u32(const void* p) {
    uint32_t a;
    asm("{ .reg .u64 t; cvta.to.shared.u64 t, %1; cvt.u32.u64 %0, t; }"
        : "=r"(a) : "l"(p));
    return a;
}
__device__ __forceinline__ __half2 h2_from_u32(uint32_t u) {
    __half2 h;
    *reinterpret_cast<uint32_t*>(&h) = u;
    return h;
}

#define CP_ASYNC16(dst, src) \
    asm volatile("cp.async.cg.shared.global [%0], [%1], 16;" \
                 :: "r"(dst), "l"(src) : "memory")
#define CP_COMMIT() asm volatile("cp.async.commit_group;" ::: "memory")
#define CP_WAIT(n)  asm volatile("cp.async.wait_group %0;" :: "n"(n) : "memory")

__device__ __forceinline__ void ldsm_x4(uint32_t addr, uint32_t* r) {
    asm volatile("ldmatrix.sync.aligned.m8n8.x4.shared.b16 {%0,%1,%2,%3}, [%4];"
                 : "=r"(r[0]), "=r"(r[1]), "=r"(r[2]), "=r"(r[3]) : "r"(addr));
}
__device__ __forceinline__ void mma_f16(float* c, const uint32_t* a,
                                        uint32_t b0, uint32_t b1) {
    asm volatile(
        "mma.sync.aligned.m16n8k16.row.col.f32.f16.f16.f32 "
        "{%0,%1,%2,%3}, {%4,%5,%6,%7}, {%8,%9}, {%0,%1,%2,%3};"
        : "+f"(c[0]), "+f"(c[1]), "+f"(c[2]), "+f"(c[3])
        : "r"(a[0]), "r"(a[1]), "r"(a[2]), "r"(a[3]), "r"(b0), "r"(b1));
}

// ============================================================
// prepconv: merged kernel.
//   blocks [0, CONV_BLKS): points fp32 -> fp16 (skip unused batches)
//   blocks [CONV_BLKS, CONV_BLKS+256): A' fp16 [j][i] + batch counts
//   NOTE: bl dropped — per-channel constants cancel in the LayerNorm.
// ============================================================
__global__ __launch_bounds__(256) void prepconv_kernel(
    const float* __restrict__ points,
    const float* __restrict__ Ww,
    const float* __restrict__ bw,
    const float* __restrict__ Wl,
    const int* __restrict__ didx) {
    const int blk = blockIdx.x;
    if (blk < CONV_BLKS) {
        const int s = blk >> 9;                  // 512 blocks per batch
        bool used = false;
#pragma unroll
        for (int b = 0; b < Bq; b++) used |= (didx[b] == s);
        if (!used) return;
        size_t idx = ((size_t)blk * 256 + threadIdx.x) * 4;
        float4 v = *reinterpret_cast<const float4*>(points + idx);
        *reinterpret_cast<__half2*>(g_Ph + idx) = __floats2half2_rn(v.x, v.y);
        *reinterpret_cast<__half2*>(g_Ph + idx + 2) = __floats2half2_rn(v.z, v.w);
        return;
    }
    if (blk == CONV_BLKS && threadIdx.x < Bq) {
        int c = 0;
#pragma unroll
        for (int b = 0; b < Bq; b++) c += (didx[b] == (int)threadIdx.x);
        g_cnt[threadIdx.x] = c;
    }
    int idx = (blk - CONV_BLKS) * 256 + threadIdx.x;   // 0 .. 65535
    int d = idx >> 14;
    int c = (idx >> 7) & (Cq - 1);
    int j = idx & (Cq - 1);
    float acc = 0.f;
#pragma unroll
    for (int w = 0; w < Wq; w++) {
        float coef = (d < 3) ? Ww[d * Wq + w] : bw[w];
        acc = fmaf(coef, Wl[(c * Wq + w) * Cq + j], acc);
    }
    int i = (d << 7) | c;
    g_Ahf[(size_t)j * 512 + i] = __float2half_rn(acc);
}

// ============================================================
// gather: S[p,i] = sum_k coef[k,d] * points_h[s, nbr[k], c]; emit fp16
//   thread handles 4 channels (c4) x 4 points via LDG.64
// ============================================================
__global__ __launch_bounds__(128, 8) void gather_kernel(
    const float* __restrict__ lc,
    const int* __restrict__ nbr) {
    __shared__ ulonglong2 s_L[TPT][Kq];
    __shared__ uint32_t s_off[TPT][Kq];

    const int tid = threadIdx.x;
    const int s = blockIdx.y;
    if (g_cnt[s] == 0) return;
    const int p0 = blockIdx.x * TPT;
    const size_t base = ((size_t)s * Pq + p0) * Kq;

    for (int i = tid; i < TPT * Kq; i += 128) {
        int t = i >> 5, k = i & 31;
        s_off[t][k] = (uint32_t)nbr[base + (size_t)t * Kq + k] << 8;   // *256B row
        const float* Lp = lc + (base + (size_t)t * Kq + k) * 3;
        s_L[t][k] = make_ulonglong2(pk2(Lp[0], Lp[1]), pk2(Lp[2], 1.0f));
    }
    __syncthreads();

    const int c4 = tid & 31;          // channel quad: channels 4*c4 .. 4*c4+3
    const int h = tid >> 5;           // 0..3 point group
    const char* ptsb = (const char*)(g_Ph + (size_t)s * Nq * Cq) + 8 * c4;

#pragma unroll 1
    for (int tt = 0; tt < 4; tt++) {
        const int t = tt * 4 + h;
        unsigned long long a01[4], a23[4];
#pragma unroll
        for (int c = 0; c < 4; c++) { a01[c] = 0ull; a23[c] = 0ull; }
#pragma unroll
        for (int k = 0; k < Kq; k++) {
            uint2 w = *reinterpret_cast<const uint2*>(ptsb + s_off[t][k]);
            float2 v0 = __half22float2(h2_from_u32(w.x));
            float2 v1 = __half22float2(h2_from_u32(w.y));
            ulonglong2 L = s_L[t][k];
            unsigned long long p0v = pk2(v0.x, v0.x), p1v = pk2(v0.y, v0.y);
            unsigned long long p2v = pk2(v1.x, v1.x), p3v = pk2(v1.y, v1.y);
            fma2(a01[0], p0v, L.x); fma2(a23[0], p0v, L.y);
            fma2(a01[1], p1v, L.x); fma2(a23[1], p1v, L.y);
            fma2(a01[2], p2v, L.x); fma2(a23[2], p2v, L.y);
            fma2(a01[3], p3v, L.x); fma2(a23[3], p3v, L.y);
        }
        const size_t rb = ((size_t)s * Pq + p0 + t) * 512;
        float2 f01[4], f23[4];
#pragma unroll
        for (int c = 0; c < 4; c++) { f01[c] = up2(a01[c]); f23[c] = up2(a23[c]); }
        uint2 st;
        __half2 ha, hb;
        ha = __floats2half2_rn(f01[0].x, f01[1].x);
        hb = __floats2half2_rn(f01[2].x, f01[3].x);
        st.x = *reinterpret_cast<uint32_t*>(&ha);
        st.y = *reinterpret_cast<uint32_t*>(&hb);
        *reinterpret_cast<uint2*>(g_S + rb + 0 * 128 + 4 * c4) = st;
        ha = __floats2half2_rn(f01[0].y, f01[1].y);
        hb = __floats2half2_rn(f01[2].y, f01[3].y);
        st.x = *reinterpret_cast<uint32_t*>(&ha);
        st.y = *reinterpret_cast<uint32_t*>(&hb);
        *reinterpret_cast<uint2*>(g_S + rb + 1 * 128 + 4 * c4) = st;
        ha = __floats2half2_rn(f23[0].x, f23[1].x);
        hb = __floats2half2_rn(f23[2].x, f23[3].x);
        st.x = *reinterpret_cast<uint32_t*>(&ha);
        st.y = *reinterpret_cast<uint32_t*>(&hb);
        *reinterpret_cast<uint2*>(g_S + rb + 2 * 128 + 4 * c4) = st;
        ha = __floats2half2_rn(f23[0].y, f23[1].y);
        hb = __floats2half2_rn(f23[2].y, f23[3].y);
        st.x = *reinterpret_cast<uint32_t*>(&ha);
        st.y = *reinterpret_cast<uint32_t*>(&hb);
        *reinterpret_cast<uint2*>(g_S + rb + 3 * 128 + 4 * c4) = st;
    }
}

// ============================================================
// GEMM: Y[p,j] = S[p,i] * A'[j,i]^T  via mma.sync fp16
//   block tile 128p x 64j; K chunks of 64 (8 chunks); 2-stage;
//   ONE barrier per chunk; 3 CTAs/SM (R13 config — no ticket/fence)
// ============================================================
#define STILE_B 18432                // 128 rows * 144B
#define ATILE_B 9216                 // 64 rows * 144B
#define OFF_S   0
#define OFF_A   (STILE_B)
#define BUF_B   (STILE_B + ATILE_B)       // 27648
#define GSM_TOTAL (2 * BUF_B)             // 55296 (epilogue 64*132*4=33792 fits)

__global__ __launch_bounds__(256, 3) void gemm_kernel() {
    extern __shared__ __align__(128) char sm[];
    const int tid = threadIdx.x;
    const int wid = tid >> 5;
    const int L = tid & 31;
    const int srcb = blockIdx.y;
    if (g_cnt[srcb] == 0) return;
    const int pt = blockIdx.x >> 1;
    const int jh = blockIdx.x & 1;     // which 64-j half
    const int wm = wid >> 1;           // 0..3  (p dim, 32 each)
    const int wn = wid & 1;            // 0..1  (j dim, 32 each)

    const uint32_t smb = smem_to_u32(sm);
    const __half* Sp = g_S + ((size_t)srcb * Pq + pt * 128) * 512;
    const __half* Ah = g_Ahf + (size_t)(jh * 64) * 512;

    float acc[2][4][4];
#pragma unroll
    for (int mt = 0; mt < 2; mt++)
#pragma unroll
        for (int nt = 0; nt < 4; nt++)
#pragma unroll
            for (int q = 0; q < 4; q++) acc[mt][nt][q] = 0.f;

    const int grp = L >> 3, lr = L & 7;
    const uint32_t aRow = (uint32_t)(wm * 32 + (grp & 1) * 8 + lr) * 144
                        + (uint32_t)(grp >> 1) * 16;
    const uint32_t bRow = (uint32_t)(wn * 32 + (grp >> 1) * 8 + lr) * 144
                        + (uint32_t)(grp & 1) * 16;

#define ISSUE(kc, buf) do {                                                     \
        uint32_t bb = smb + (uint32_t)(buf) * BUF_B;                            \
        _Pragma("unroll")                                                       \
        for (int ii = 0; ii < 4; ii++) {                                        \
            int u = tid + ii * 256;                                             \
            int row = u >> 3, seg = u & 7;                                      \
            CP_ASYNC16(bb + OFF_S + (uint32_t)row * 144 + (uint32_t)seg * 16,   \
                       (const char*)(Sp + (size_t)row * 512 + (kc) * 64 + seg * 8)); \
        }                                                                       \
        _Pragma("unroll")                                                       \
        for (int ii = 0; ii < 2; ii++) {                                        \
            int u = tid + ii * 256;                                             \
            int row = u >> 3, seg = u & 7;                                      \
            CP_ASYNC16(bb + OFF_A + (uint32_t)row * 144 + (uint32_t)seg * 16,   \
                       (const char*)(Ah + (size_t)row * 512 + (kc) * 64 + seg * 8)); \
        }                                                                       \
        CP_COMMIT();                                                            \
    } while (0)

    ISSUE(0, 0);

#pragma unroll 1
    for (int kc = 0; kc < 8; kc++) {
        CP_WAIT(0);
        __syncthreads();
        if (kc < 7) ISSUE(kc + 1, (kc + 1) & 1);   // safe: readers passed sync

        const uint32_t bb = smb + (uint32_t)(kc & 1) * BUF_B;
#pragma unroll
        for (int ks = 0; ks < 4; ks++) {
            uint32_t af[2][4];
#pragma unroll
            for (int mt = 0; mt < 2; mt++) {
                uint32_t ao = aRow + (uint32_t)mt * (16 * 144) + (uint32_t)ks * 32;
                ldsm_x4(bb + OFF_S + ao, af[mt]);
            }
#pragma unroll
            for (int ng = 0; ng < 2; ng++) {
                uint32_t bh[4];
                uint32_t bo = bRow + (uint32_t)ng * (16 * 144) + (uint32_t)ks * 32;
                ldsm_x4(bb + OFF_A + bo, bh);
#pragma unroll
                for (int mt = 0; mt < 2; mt++) {
#pragma unroll
                    for (int t2 = 0; t2 < 2; t2++) {
                        mma_f16(acc[mt][2 * ng + t2], af[mt],
                                bh[2 * t2], bh[2 * t2 + 1]);
                    }
                }
            }
        }
    }
    __syncthreads();

    // ---- epilogue: C frags -> smem [64j][132] -> coalesced fp16 Y + LN partials ----
    float* yt = (float*)sm;
    {
        const int pb = wm * 32 + (L >> 2);
        const int jb = wn * 32 + ((L & 3) << 1);
#pragma unroll
        for (int mt = 0; mt < 2; mt++) {
#pragma unroll
            for (int nt = 0; nt < 4; nt++) {
                const float* c = acc[mt][nt];
                int p = pb + mt * 16;
                int j = jb + nt * 8;
                yt[j * 132 + p] = c[0];
                yt[(j + 1) * 132 + p] = c[1];
                yt[j * 132 + p + 8] = c[2];
                yt[(j + 1) * 132 + p + 8] = c[3];
            }
        }
    }
    __syncthreads();

    const int blk2 = srcb * NPTILE + pt;
#pragma unroll 1
    for (int rr = 0; rr < 8; rr++) {
        int j = wid * 8 + rr;          // local j in [0,64)
        int jg = jh * 64 + j;          // global output channel
        float4 v = *reinterpret_cast<const float4*>(yt + j * 132 + L * 4);
        __half2 h0 = __floats2half2_rn(v.x, v.y);
        __half2 h1 = __floats2half2_rn(v.z, v.w);
        uint2 st;
        st.x = *reinterpret_cast<uint32_t*>(&h0);
        st.y = *reinterpret_cast<uint32_t*>(&h1);
        *reinterpret_cast<uint2*>(
            g_Yth + ((size_t)srcb * Cq + jg) * Pq + pt * 128 + L * 4) = st;
        float ls = (v.x + v.y) + (v.z + v.w);
        float lq = (v.x * v.x + v.y * v.y) + (v.z * v.z + v.w * v.w);
#pragma unroll
        for (int o = 16; o > 0; o >>= 1) {
            ls += __shfl_xor_sync(0xFFFFFFFFu, ls, o);
            lq += __shfl_xor_sync(0xFFFFFFFFu, lq, o);
        }
        if (L == 0) {
            g_ps[(size_t)blk2 * Cq + jg] = ls;
            g_pq[(size_t)blk2 * Cq + jg] = lq;
        }
    }
}

// ============================================================
// out: per-block LN-stat reduction (deterministic tree over 256 rows,
//   identical in every block) + scale/shift/relu coalesced copy.
//   Runs after gemm completes, so partials are globally visible —
//   no fence/ticket needed (that was R14's mistake).
// ============================================================
__global__ __launch_bounds__(256) void out_kernel(float* __restrict__ out,
                                                  const int* __restrict__ didx,
                                                  const float* __restrict__ gamma,
                                                  const float* __restrict__ beta) {
    __shared__ float red_s[256], red_q[256];
    const int tid = threadIdx.x;
    const int b = blockIdx.x >> 7;
    const int j = blockIdx.x & 127;
    const int src = didx[b];

    // weighted partial for row tid
    {
        float w = (float)g_cnt[tid >> 5];
        red_s[tid] = w * g_ps[(size_t)tid * Cq + j];
        red_q[tid] = w * g_pq[(size_t)tid * Cq + j];
    }
    __syncthreads();
#pragma unroll
    for (int o = 128; o > 0; o >>= 1) {
        if (tid < o) {
            red_s[tid] += red_s[tid + o];
            red_q[tid] += red_q[tid + o];
        }
        __syncthreads();
    }
    const float inv = 1.0f / (float)(Bq * Pq);
    const float mean = red_s[0] * inv;
    const float var = red_q[0] * inv - mean * mean;
    const float sc = rsqrtf(var + EPSq) * gamma[j];
    const float sh = beta[j] - mean * sc;

    const uint4* in = reinterpret_cast<const uint4*>(
        g_Yth + ((size_t)src * Cq + j) * Pq);
    float4* op = reinterpret_cast<float4*>(out + (size_t)blockIdx.x * Pq);
#pragma unroll
    for (int k = 0; k < 2; k++) {
        int idx = tid + k * 256;              // 512 uint4 per row
        uint4 v = in[idx];
        float2 a0 = __half22float2(h2_from_u32(v.x));
        float2 a1 = __half22float2(h2_from_u32(v.y));
        float2 a2 = __half22float2(h2_from_u32(v.z));
        float2 a3 = __half22float2(h2_from_u32(v.w));
        float4 o0, o1;
        o0.x = fmaxf(fmaf(a0.x, sc, sh), 0.f);
        o0.y = fmaxf(fmaf(a0.y, sc, sh), 0.f);
        o0.z = fmaxf(fmaf(a1.x, sc, sh), 0.f);
        o0.w = fmaxf(fmaf(a1.y, sc, sh), 0.f);
        o1.x = fmaxf(fmaf(a2.x, sc, sh), 0.f);
        o1.y = fmaxf(fmaf(a2.y, sc, sh), 0.f);
        o1.z = fmaxf(fmaf(a3.x, sc, sh), 0.f);
        o1.w = fmaxf(fmaf(a3.y, sc, sh), 0.f);
        op[idx * 2] = o0;
        op[idx * 2 + 1] = o1;
    }
}

// ============================================================
// Launch
// ============================================================
extern "C" void kernel_launch(void* const* d_in, const int* in_sizes, int n_in,
                              void* d_out, int out_size) {
    const float* xyz    = (const float*)d_in[0];
    const float* points = (const float*)d_in[1];
    const float* lc     = (const float*)d_in[2];
    const int*   nbr    = (const int*)d_in[3];
    const int*   didx   = (const int*)d_in[4];
    const float* Ww     = (const float*)d_in[5];
    const float* bw     = (const float*)d_in[6];
    const float* Wl     = (const float*)d_in[7];
    const float* gamma  = (const float*)d_in[9];
    const float* beta   = (const float*)d_in[10];
    float* out = (float*)d_out;

    cudaMemcpyAsync(out, xyz, (size_t)Bq * Pq * 3 * sizeof(float),
                    cudaMemcpyDeviceToDevice, 0);

    cudaFuncSetAttribute(gemm_kernel,
                         cudaFuncAttributeMaxDynamicSharedMemorySize, GSM_TOTAL);

    prepconv_kernel<<<CONV_BLKS + 256, 256>>>(points, Ww, bw, Wl, didx);

    dim3 gg(GBLK_PER_B, Bq);
    gather_kernel<<<gg, 128>>>(lc, nbr);

    dim3 g2(NPTILE * 2, Bq);
    gemm_kernel<<<g2, 256, GSM_TOTAL>>>();

    out_kernel<<<Bq * Cq, 256>>>(out + (size_t)Bq * Pq * 3, didx, gamma, beta);
}

// round 16
// speedup vs baseline: 1.1868x; 1.0160x over previous
#include <cuda_runtime.h>
#include <cuda_bf16.h>
#include <cuda_fp16.h>
#include <cstdint>
#include <cstddef>

// Problem constants
#define Bq 8
#define Nq 4096
#define Pq 4096
#define Kq 32
#define Cq 128
#define Wq 16
#define EPSq 1e-5f

#define TPT 16                        // points per gather block
#define GBLK_PER_B (Pq / TPT)         // 256
#define NPTILE (Pq / 128)             // 32 p-tiles per batch
#define NBLK2 (Bq * NPTILE)           // 256 stat rows
#define CONV_BLKS 4096                // convert blocks in merged prep kernel

// ------------------- device globals (no allocation allowed) -------------------
__device__ __align__(256) __half g_Ph[(size_t)Bq * Nq * Cq];     // fp16 points
__device__ __align__(256) __half g_S[(size_t)Bq * Pq * 512];     // fp16 S, [s][p][i]
__device__ __align__(256) __half g_Ahf[128 * 512];               // A' fp16, [j][i]
__device__ __align__(256) __half g_Yth[(size_t)Bq * Cq * Pq];    // fp16 Y, [s][j][p]
__device__ float g_ps[NBLK2 * Cq];
__device__ float g_pq[NBLK2 * Cq];
__device__ int   g_cnt[Bq];

// ------------------- helpers -------------------
__device__ __forceinline__ unsigned long long pk2(float x, float y) {
    unsigned long long r;
    asm("mov.b64 %0, {%1,%2};" : "=l"(r) : "f"(x), "f"(y));
    return r;
}
__device__ __forceinline__ void fma2(unsigned long long& d,
                                     unsigned long long a,
                                     unsigned long long b) {
    asm("fma.rn.f32x2 %0, %1, %2, %0;" : "+l"(d) : "l"(a), "l"(b));
}
__device__ __forceinline__ float2 up2(unsigned long long v) {
    float x, y;
    asm("mov.b64 {%0,%1}, %2;" : "=f"(x), "=f"(y) : "l"(v));
    return make_float2(x, y);
}
__device__ __forceinline__ uint32_t smem_to_u32(const void* p) {
    uint32_t a;
    asm("{ .reg .u64 t; cvta.to.shared.u64 t, %1; cvt.u32.u64 %0, t; }"
        : "=r"(a) : "l"(p));
    return a;
}
__device__ __forceinline__ __half2 h2_from_u32(uint32_t u) {
    __half2 h;
    *reinterpret_cast<uint32_t*>(&h) = u;
    return h;
}
__device__ __forceinline__ uint32_t u32_from_h2(__half2 h) {
    return *reinterpret_cast<uint32_t*>(&h);
}

#define CP_ASYNC16(dst, src) \
    asm volatile("cp.async.cg.shared.global [%0], [%1], 16;" \
                 :: "r"(dst), "l"(src) : "memory")
#define CP_COMMIT() asm volatile("cp.async.commit_group;" ::: "memory")
#define CP_WAIT(n)  asm volatile("cp.async.wait_group %0;" :: "n"(n) : "memory")

__device__ __forceinline__ void ldsm_x4(uint32_t addr, uint32_t* r) {
    asm volatile("ldmatrix.sync.aligned.m8n8.x4.shared.b16 {%0,%1,%2,%3}, [%4];"
                 : "=r"(r[0]), "=r"(r[1]), "=r"(r[2]), "=r"(r[3]) : "r"(addr));
}
__device__ __forceinline__ void mma_f16(float* c, const uint32_t* a,
                                        uint32_t b0, uint32_t b1) {
    asm volatile(
        "mma.sync.aligned.m16n8k16.row.col.f32.f16.f16.f32 "
        "{%0,%1,%2,%3}, {%4,%5,%6,%7}, {%8,%9}, {%0,%1,%2,%3};"
        : "+f"(c[0]), "+f"(c[1]), "+f"(c[2]), "+f"(c[3])
        : "r"(a[0]), "r"(a[1]), "r"(a[2]), "r"(a[3]), "r"(b0), "r"(b1));
}

// ============================================================
// prepconv: merged kernel.
//   blocks [0, CONV_BLKS): points fp32 -> fp16 (skip unused batches)
//   blocks [CONV_BLKS, CONV_BLKS+256): A' fp16 [j][i] + batch counts
//   NOTE: bl dropped — per-channel constants cancel in the LayerNorm.
// ============================================================
__global__ __launch_bounds__(256) void prepconv_kernel(
    const float* __restrict__ points,
    const float* __restrict__ Ww,
    const float* __restrict__ bw,
    const float* __restrict__ Wl,
    const int* __restrict__ didx) {
    const int blk = blockIdx.x;
    if (blk < CONV_BLKS) {
        const int s = blk >> 9;                  // 512 blocks per batch
        bool used = false;
#pragma unroll
        for (int b = 0; b < Bq; b++) used |= (didx[b] == s);
        if (!used) return;
        size_t idx = ((size_t)blk * 256 + threadIdx.x) * 4;
        float4 v = *reinterpret_cast<const float4*>(points + idx);
        *reinterpret_cast<__half2*>(g_Ph + idx) = __floats2half2_rn(v.x, v.y);
        *reinterpret_cast<__half2*>(g_Ph + idx + 2) = __floats2half2_rn(v.z, v.w);
        return;
    }
    if (blk == CONV_BLKS && threadIdx.x < Bq) {
        int c = 0;
#pragma unroll
        for (int b = 0; b < Bq; b++) c += (didx[b] == (int)threadIdx.x);
        g_cnt[threadIdx.x] = c;
    }
    int idx = (blk - CONV_BLKS) * 256 + threadIdx.x;   // 0 .. 65535
    int d = idx >> 14;
    int c = (idx >> 7) & (Cq - 1);
    int j = idx & (Cq - 1);
    float acc = 0.f;
#pragma unroll
    for (int w = 0; w < Wq; w++) {
        float coef = (d < 3) ? Ww[d * Wq + w] : bw[w];
        acc = fmaf(coef, Wl[(c * Wq + w) * Cq + j], acc);
    }
    int i = (d << 7) | c;
    g_Ahf[(size_t)j * 512 + i] = __float2half_rn(acc);
}

// ============================================================
// gather: S[p,i] = sum_k coef[k,d] * points_h[s, nbr[k], c]; emit fp16
//   thread handles 8 channels (c8) via LDG.128; 16 lanes cover a 256B row
// ============================================================
__global__ __launch_bounds__(128, 6) void gather_kernel(
    const float* __restrict__ lc,
    const int* __restrict__ nbr) {
    __shared__ ulonglong2 s_L[TPT][Kq];
    __shared__ uint32_t s_off[TPT][Kq];

    const int tid = threadIdx.x;
    const int s = blockIdx.y;
    if (g_cnt[s] == 0) return;
    const int p0 = blockIdx.x * TPT;
    const size_t base = ((size_t)s * Pq + p0) * Kq;

    for (int i = tid; i < TPT * Kq; i += 128) {
        int t = i >> 5, k = i & 31;
        s_off[t][k] = (uint32_t)nbr[base + (size_t)t * Kq + k] << 8;   // *256B row
        const float* Lp = lc + (base + (size_t)t * Kq + k) * 3;
        s_L[t][k] = make_ulonglong2(pk2(Lp[0], Lp[1]), pk2(Lp[2], 1.0f));
    }
    __syncthreads();

    const int c8 = tid & 15;          // channel octet: channels 8*c8 .. 8*c8+7
    const int h = tid >> 4;           // 0..7 point group
    const char* ptsb = (const char*)(g_Ph + (size_t)s * Nq * Cq) + 16 * c8;

#pragma unroll 1
    for (int tt = 0; tt < 2; tt++) {
        const int t = tt * 8 + h;
        unsigned long long a01[8], a23[8];
#pragma unroll
        for (int c = 0; c < 8; c++) { a01[c] = 0ull; a23[c] = 0ull; }
#pragma unroll 8
        for (int k = 0; k < Kq; k++) {
            uint4 w = *reinterpret_cast<const uint4*>(ptsb + s_off[t][k]);
            ulonglong2 L = s_L[t][k];
            float2 v0 = __half22float2(h2_from_u32(w.x));
            float2 v1 = __half22float2(h2_from_u32(w.y));
            float2 v2 = __half22float2(h2_from_u32(w.z));
            float2 v3 = __half22float2(h2_from_u32(w.w));
            unsigned long long pv;
            pv = pk2(v0.x, v0.x); fma2(a01[0], pv, L.x); fma2(a23[0], pv, L.y);
            pv = pk2(v0.y, v0.y); fma2(a01[1], pv, L.x); fma2(a23[1], pv, L.y);
            pv = pk2(v1.x, v1.x); fma2(a01[2], pv, L.x); fma2(a23[2], pv, L.y);
            pv = pk2(v1.y, v1.y); fma2(a01[3], pv, L.x); fma2(a23[3], pv, L.y);
            pv = pk2(v2.x, v2.x); fma2(a01[4], pv, L.x); fma2(a23[4], pv, L.y);
            pv = pk2(v2.y, v2.y); fma2(a01[5], pv, L.x); fma2(a23[5], pv, L.y);
            pv = pk2(v3.x, v3.x); fma2(a01[6], pv, L.x); fma2(a23[6], pv, L.y);
            pv = pk2(v3.y, v3.y); fma2(a01[7], pv, L.x); fma2(a23[7], pv, L.y);
        }
        const size_t rb = ((size_t)s * Pq + p0 + t) * 512;
        float2 f01[8], f23[8];
#pragma unroll
        for (int c = 0; c < 8; c++) { f01[c] = up2(a01[c]); f23[c] = up2(a23[c]); }
        uint4 st;
        // d = 0
        st.x = u32_from_h2(__floats2half2_rn(f01[0].x, f01[1].x));
        st.y = u32_from_h2(__floats2half2_rn(f01[2].x, f01[3].x));
        st.z = u32_from_h2(__floats2half2_rn(f01[4].x, f01[5].x));
        st.w = u32_from_h2(__floats2half2_rn(f01[6].x, f01[7].x));
        *reinterpret_cast<uint4*>(g_S + rb + 0 * 128 + 8 * c8) = st;
        // d = 1
        st.x = u32_from_h2(__floats2half2_rn(f01[0].y, f01[1].y));
        st.y = u32_from_h2(__floats2half2_rn(f01[2].y, f01[3].y));
        st.z = u32_from_h2(__floats2half2_rn(f01[4].y, f01[5].y));
        st.w = u32_from_h2(__floats2half2_rn(f01[6].y, f01[7].y));
        *reinterpret_cast<uint4*>(g_S + rb + 1 * 128 + 8 * c8) = st;
        // d = 2
        st.x = u32_from_h2(__floats2half2_rn(f23[0].x, f23[1].x));
        st.y = u32_from_h2(__floats2half2_rn(f23[2].x, f23[3].x));
        st.z = u32_from_h2(__floats2half2_rn(f23[4].x, f23[5].x));
        st.w = u32_from_h2(__floats2half2_rn(f23[6].x, f23[7].x));
        *reinterpret_cast<uint4*>(g_S + rb + 2 * 128 + 8 * c8) = st;
        // d = 3
        st.x = u32_from_h2(__floats2half2_rn(f23[0].y, f23[1].y));
        st.y = u32_from_h2(__floats2half2_rn(f23[2].y, f23[3].y));
        st.z = u32_from_h2(__floats2half2_rn(f23[4].y, f23[5].y));
        st.w = u32_from_h2(__floats2half2_rn(f23[6].y, f23[7].y));
        *reinterpret_cast<uint4*>(g_S + rb + 3 * 128 + 8 * c8) = st;
    }
}

// ============================================================
// GEMM: Y[p,j] = S[p,i] * A'[j,i]^T  via mma.sync fp16
//   block tile 128p x 64j; K chunks of 64 (8 chunks); 2-stage;
//   ONE barrier per chunk; 3 CTAs/SM (R13/R15 config)
// ============================================================
#define STILE_B 18432                // 128 rows * 144B
#define ATILE_B 9216                 // 64 rows * 144B
#define OFF_S   0
#define OFF_A   (STILE_B)
#define BUF_B   (STILE_B + ATILE_B)       // 27648
#define GSM_TOTAL (2 * BUF_B)             // 55296 (epilogue 64*132*4=33792 fits)

__global__ __launch_bounds__(256, 3) void gemm_kernel() {
    extern __shared__ __align__(128) char sm[];
    const int tid = threadIdx.x;
    const int wid = tid >> 5;
    const int L = tid & 31;
    const int srcb = blockIdx.y;
    if (g_cnt[srcb] == 0) return;
    const int pt = blockIdx.x >> 1;
    const int jh = blockIdx.x & 1;     // which 64-j half
    const int wm = wid >> 1;           // 0..3  (p dim, 32 each)
    const int wn = wid & 1;            // 0..1  (j dim, 32 each)

    const uint32_t smb = smem_to_u32(sm);
    const __half* Sp = g_S + ((size_t)srcb * Pq + pt * 128) * 512;
    const __half* Ah = g_Ahf + (size_t)(jh * 64) * 512;

    float acc[2][4][4];
#pragma unroll
    for (int mt = 0; mt < 2; mt++)
#pragma unroll
        for (int nt = 0; nt < 4; nt++)
#pragma unroll
            for (int q = 0; q < 4; q++) acc[mt][nt][q] = 0.f;

    const int grp = L >> 3, lr = L & 7;
    const uint32_t aRow = (uint32_t)(wm * 32 + (grp & 1) * 8 + lr) * 144
                        + (uint32_t)(grp >> 1) * 16;
    const uint32_t bRow = (uint32_t)(wn * 32 + (grp >> 1) * 8 + lr) * 144
                        + (uint32_t)(grp & 1) * 16;

#define ISSUE(kc, buf) do {                                                     \
        uint32_t bb = smb + (uint32_t)(buf) * BUF_B;                            \
        _Pragma("unroll")                                                       \
        for (int ii = 0; ii < 4; ii++) {                                        \
            int u = tid + ii * 256;                                             \
            int row = u >> 3, seg = u & 7;                                      \
            CP_ASYNC16(bb + OFF_S + (uint32_t)row * 144 + (uint32_t)seg * 16,   \
                       (const char*)(Sp + (size_t)row * 512 + (kc) * 64 + seg * 8)); \
        }                                                                       \
        _Pragma("unroll")                                                       \
        for (int ii = 0; ii < 2; ii++) {                                        \
            int u = tid + ii * 256;                                             \
            int row = u >> 3, seg = u & 7;                                      \
            CP_ASYNC16(bb + OFF_A + (uint32_t)row * 144 + (uint32_t)seg * 16,   \
                       (const char*)(Ah + (size_t)row * 512 + (kc) * 64 + seg * 8)); \
        }                                                                       \
        CP_COMMIT();                                                            \
    } while (0)

    ISSUE(0, 0);

#pragma unroll 1
    for (int kc = 0; kc < 8; kc++) {
        CP_WAIT(0);
        __syncthreads();
        if (kc < 7) ISSUE(kc + 1, (kc + 1) & 1);   // safe: readers passed sync

        const uint32_t bb = smb + (uint32_t)(kc & 1) * BUF_B;
#pragma unroll
        for (int ks = 0; ks < 4; ks++) {
            uint32_t af[2][4];
#pragma unroll
            for (int mt = 0; mt < 2; mt++) {
                uint32_t ao = aRow + (uint32_t)mt * (16 * 144) + (uint32_t)ks * 32;
                ldsm_x4(bb + OFF_S + ao, af[mt]);
            }
#pragma unroll
            for (int ng = 0; ng < 2; ng++) {
                uint32_t bh[4];
                uint32_t bo = bRow + (uint32_t)ng * (16 * 144) + (uint32_t)ks * 32;
                ldsm_x4(bb + OFF_A + bo, bh);
#pragma unroll
                for (int mt = 0; mt < 2; mt++) {
#pragma unroll
                    for (int t2 = 0; t2 < 2; t2++) {
                        mma_f16(acc[mt][2 * ng + t2], af[mt],
                                bh[2 * t2], bh[2 * t2 + 1]);
                    }
                }
            }
        }
    }
    __syncthreads();

    // ---- epilogue: C frags -> smem [64j][132] -> coalesced fp16 Y + LN partials ----
    float* yt = (float*)sm;
    {
        const int pb = wm * 32 + (L >> 2);
        const int jb = wn * 32 + ((L & 3) << 1);
#pragma unroll
        for (int mt = 0; mt < 2; mt++) {
#pragma unroll
            for (int nt = 0; nt < 4; nt++) {
                const float* c = acc[mt][nt];
                int p = pb + mt * 16;
                int j = jb + nt * 8;
                yt[j * 132 + p] = c[0];
                yt[(j + 1) * 132 + p] = c[1];
                yt[j * 132 + p + 8] = c[2];
                yt[(j + 1) * 132 + p + 8] = c[3];
            }
        }
    }
    __syncthreads();

    const int blk2 = srcb * NPTILE + pt;
#pragma unroll 1
    for (int rr = 0; rr < 8; rr++) {
        int j = wid * 8 + rr;          // local j in [0,64)
        int jg = jh * 64 + j;          // global output channel
        float4 v = *reinterpret_cast<const float4*>(yt + j * 132 + L * 4);
        __half2 h0 = __floats2half2_rn(v.x, v.y);
        __half2 h1 = __floats2half2_rn(v.z, v.w);
        uint2 st;
        st.x = *reinterpret_cast<uint32_t*>(&h0);
        st.y = *reinterpret_cast<uint32_t*>(&h1);
        *reinterpret_cast<uint2*>(
            g_Yth + ((size_t)srcb * Cq + jg) * Pq + pt * 128 + L * 4) = st;
        float ls = (v.x + v.y) + (v.z + v.w);
        float lq = (v.x * v.x + v.y * v.y) + (v.z * v.z + v.w * v.w);
#pragma unroll
        for (int o = 16; o > 0; o >>= 1) {
            ls += __shfl_xor_sync(0xFFFFFFFFu, ls, o);
            lq += __shfl_xor_sync(0xFFFFFFFFu, lq, o);
        }
        if (L == 0) {
            g_ps[(size_t)blk2 * Cq + jg] = ls;
            g_pq[(size_t)blk2 * Cq + jg] = lq;
        }
    }
}

// ============================================================
// out: per-block LN-stat reduction (warp shuffles + 1 sync; fixed order,
//   identical in every block -> deterministic) + scale/shift/relu copy.
// ============================================================
__global__ __launch_bounds__(256) void out_kernel(float* __restrict__ out,
                                                  const int* __restrict__ didx,
                                                  const float* __restrict__ gamma,
                                                  const float* __restrict__ beta) {
    __shared__ float red_s[8], red_q[8];
    const int tid = threadIdx.x;
    const int b = blockIdx.x >> 7;
    const int j = blockIdx.x & 127;
    const int src = didx[b];

    // weighted partial for row tid; warp-reduce; 8 warp sums; broadcast sum
    {
        float w = (float)g_cnt[tid >> 5];
        float s = w * g_ps[(size_t)tid * Cq + j];
        float q = w * g_pq[(size_t)tid * Cq + j];
#pragma unroll
        for (int o = 16; o > 0; o >>= 1) {
            s += __shfl_xor_sync(0xFFFFFFFFu, s, o);
            q += __shfl_xor_sync(0xFFFFFFFFu, q, o);
        }
        if ((tid & 31) == 0) {
            red_s[tid >> 5] = s;
            red_q[tid >> 5] = q;
        }
    }
    __syncthreads();
    float S = ((red_s[0] + red_s[1]) + (red_s[2] + red_s[3]))
            + ((red_s[4] + red_s[5]) + (red_s[6] + red_s[7]));
    float Q = ((red_q[0] + red_q[1]) + (red_q[2] + red_q[3]))
            + ((red_q[4] + red_q[5]) + (red_q[6] + red_q[7]));
    const float inv = 1.0f / (float)(Bq * Pq);
    const float mean = S * inv;
    const float var = Q * inv - mean * mean;
    const float sc = rsqrtf(var + EPSq) * gamma[j];
    const float sh = beta[j] - mean * sc;

    const uint4* in = reinterpret_cast<const uint4*>(
        g_Yth + ((size_t)src * Cq + j) * Pq);
    float4* op = reinterpret_cast<float4*>(out + (size_t)blockIdx.x * Pq);
#pragma unroll
    for (int k = 0; k < 2; k++) {
        int idx = tid + k * 256;              // 512 uint4 per row
        uint4 v = in[idx];
        float2 a0 = __half22float2(h2_from_u32(v.x));
        float2 a1 = __half22float2(h2_from_u32(v.y));
        float2 a2 = __half22float2(h2_from_u32(v.z));
        float2 a3 = __half22float2(h2_from_u32(v.w));
        float4 o0, o1;
        o0.x = fmaxf(fmaf(a0.x, sc, sh), 0.f);
        o0.y = fmaxf(fmaf(a0.y, sc, sh), 0.f);
        o0.z = fmaxf(fmaf(a1.x, sc, sh), 0.f);
        o0.w = fmaxf(fmaf(a1.y, sc, sh), 0.f);
        o1.x = fmaxf(fmaf(a2.x, sc, sh), 0.f);
        o1.y = fmaxf(fmaf(a2.y, sc, sh), 0.f);
        o1.z = fmaxf(fmaf(a3.x, sc, sh), 0.f);
        o1.w = fmaxf(fmaf(a3.y, sc, sh), 0.f);
        op[idx * 2] = o0;
        op[idx * 2 + 1] = o1;
    }
}

// ============================================================
// Launch
// ============================================================
extern "C" void kernel_launch(void* const* d_in, const int* in_sizes, int n_in,
                              void* d_out, int out_size) {
    const float* xyz    = (const float*)d_in[0];
    const float* points = (const float*)d_in[1];
    const float* lc     = (const float*)d_in[2];
    const int*   nbr    = (const int*)d_in[3];
    const int*   didx   = (const int*)d_in[4];
    const float* Ww     = (const float*)d_in[5];
    const float* bw     = (const float*)d_in[6];
    const float* Wl     = (const float*)d_in[7];
    const float* gamma  = (const float*)d_in[9];
    const float* beta   = (const float*)d_in[10];
    float* out = (float*)d_out;

    cudaMemcpyAsync(out, xyz, (size_t)Bq * Pq * 3 * sizeof(float),
                    cudaMemcpyDeviceToDevice, 0);

    cudaFuncSetAttribute(gemm_kernel,
                         cudaFuncAttributeMaxDynamicSharedMemorySize, GSM_TOTAL);

    prepconv_kernel<<<CONV_BLKS + 256, 256>>>(points, Ww, bw, Wl, didx);

    dim3 gg(GBLK_PER_B, Bq);
    gather_kernel<<<gg, 128>>>(lc, nbr);

    dim3 g2(NPTILE * 2, Bq);
    gemm_kernel<<<g2, 256, GSM_TOTAL>>>();

    out_kernel<<<Bq * Cq, 256>>>(out + (size_t)Bq * Pq * 3, didx, gamma, beta);
}

// round 17
// speedup vs baseline: 1.2266x; 1.0335x over previous
#include <cuda_runtime.h>
#include <cuda_bf16.h>
#include <cuda_fp16.h>
#include <cstdint>
#include <cstddef>

// Problem constants
#define Bq 8
#define Nq 4096
#define Pq 4096
#define Kq 32
#define Cq 128
#define Wq 16
#define EPSq 1e-5f

#define TPT 16                        // points per gather block
#define GBLK_PER_B (Pq / TPT)         // 256
#define NPTILE (Pq / 128)             // 32 p-tiles per batch
#define NBLK2 (Bq * NPTILE)           // 256 stat rows
#define CONV_BLKS 4096                // convert blocks in merged prep kernel

// ------------------- device globals (no allocation allowed) -------------------
__device__ __align__(256) __half g_Ph[(size_t)Bq * Nq * Cq];     // fp16 points
__device__ __align__(256) __half g_S[(size_t)Bq * Pq * 512];     // fp16 S, [s][p][i]
__device__ __align__(256) __half g_Ahf[128 * 512];               // A' fp16, [j][i]
__device__ __align__(256) __half g_Yth[(size_t)Bq * Cq * Pq];    // fp16 Y, [s][j][p]
__device__ float g_ps[NBLK2 * Cq];
__device__ float g_pq[NBLK2 * Cq];
__device__ int   g_cnt[Bq];

// ------------------- helpers -------------------
__device__ __forceinline__ unsigned long long pk2(float x, float y) {
    unsigned long long r;
    asm("mov.b64 %0, {%1,%2};" : "=l"(r) : "f"(x), "f"(y));
    return r;
}
__device__ __forceinline__ void fma2(unsigned long long& d,
                                     unsigned long long a,
                                     unsigned long long b) {
    asm("fma.rn.f32x2 %0, %1, %2, %0;" : "+l"(d) : "l"(a), "l"(b));
}
__device__ __forceinline__ float2 up2(unsigned long long v) {
    float x, y;
    asm("mov.b64 {%0,%1}, %2;" : "=f"(x), "=f"(y) : "l"(v));
    return make_float2(x, y);
}
__device__ __forceinline__ uint32_t smem_to_u32(const void* p) {
    uint32_t a;
    asm("{ .reg .u64 t; cvta.to.shared.u64 t, %1; cvt.u32.u64 %0, t; }"
        : "=r"(a) : "l"(p));
    return a;
}
__device__ __forceinline__ __half2 h2_from_u32(uint32_t u) {
    __half2 h;
    *reinterpret_cast<uint32_t*>(&h) = u;
    return h;
}
__device__ __forceinline__ uint32_t u32_from_h2(__half2 h) {
    return *reinterpret_cast<uint32_t*>(&h);
}

#define CP_ASYNC16(dst, src) \
    asm volatile("cp.async.cg.shared.global [%0], [%1], 16;" \
                 :: "r"(dst), "l"(src) : "memory")
#define CP_COMMIT() asm volatile("cp.async.commit_group;" ::: "memory")
#define CP_WAIT(n)  asm volatile("cp.async.wait_group %0;" :: "n"(n) : "memory")

__device__ __forceinline__ void ldsm_x4(uint32_t addr, uint32_t* r) {
    asm volatile("ldmatrix.sync.aligned.m8n8.x4.shared.b16 {%0,%1,%2,%3}, [%4];"
                 : "=r"(r[0]), "=r"(r[1]), "=r"(r[2]), "=r"(r[3]) : "r"(addr));
}
__device__ __forceinline__ void mma_f16(float* c, const uint32_t* a,
                                        uint32_t b0, uint32_t b1) {
    asm volatile(
        "mma.sync.aligned.m16n8k16.row.col.f32.f16.f16.f32 "
        "{%0,%1,%2,%3}, {%4,%5,%6,%7}, {%8,%9}, {%0,%1,%2,%3};"
        : "+f"(c[0]), "+f"(c[1]), "+f"(c[2]), "+f"(c[3])
        : "r"(a[0]), "r"(a[1]), "r"(a[2]), "r"(a[3]), "r"(b0), "r"(b1));
}

// ============================================================
// prepconv: merged kernel.
//   blocks [0, CONV_BLKS): points fp32 -> fp16 (skip unused batches)
//   blocks [CONV_BLKS, CONV_BLKS+256): A' fp16 [j][i] + batch counts
//   NOTE: bl dropped — per-channel constants cancel in the LayerNorm.
// ============================================================
__global__ __launch_bounds__(256) void prepconv_kernel(
    const float* __restrict__ points,
    const float* __restrict__ Ww,
    const float* __restrict__ bw,
    const float* __restrict__ Wl,
    const int* __restrict__ didx) {
    const int blk = blockIdx.x;
    if (blk < CONV_BLKS) {
        const int s = blk >> 9;                  // 512 blocks per batch
        bool used = false;
#pragma unroll
        for (int b = 0; b < Bq; b++) used |= (didx[b] == s);
        if (!used) return;
        size_t idx = ((size_t)blk * 256 + threadIdx.x) * 4;
        float4 v = *reinterpret_cast<const float4*>(points + idx);
        *reinterpret_cast<__half2*>(g_Ph + idx) = __floats2half2_rn(v.x, v.y);
        *reinterpret_cast<__half2*>(g_Ph + idx + 2) = __floats2half2_rn(v.z, v.w);
        return;
    }
    if (blk == CONV_BLKS && threadIdx.x < Bq) {
        int c = 0;
#pragma unroll
        for (int b = 0; b < Bq; b++) c += (didx[b] == (int)threadIdx.x);
        g_cnt[threadIdx.x] = c;
    }
    int idx = (blk - CONV_BLKS) * 256 + threadIdx.x;   // 0 .. 65535
    int d = idx >> 14;
    int c = (idx >> 7) & (Cq - 1);
    int j = idx & (Cq - 1);
    float acc = 0.f;
#pragma unroll
    for (int w = 0; w < Wq; w++) {
        float coef = (d < 3) ? Ww[d * Wq + w] : bw[w];
        acc = fmaf(coef, Wl[(c * Wq + w) * Cq + j], acc);
    }
    int i = (d << 7) | c;
    g_Ahf[(size_t)j * 512 + i] = __float2half_rn(acc);
}

// ============================================================
// gather: S[p,i] = sum_k coef[k,d] * points_h[s, nbr[k], c]; emit fp16
//   thread handles 8 channels (c8) via LDG.128; 16 lanes cover a 256B row
// ============================================================
__global__ __launch_bounds__(128, 6) void gather_kernel(
    const float* __restrict__ lc,
    const int* __restrict__ nbr) {
    __shared__ ulonglong2 s_L[TPT][Kq];
    __shared__ uint32_t s_off[TPT][Kq];

    const int tid = threadIdx.x;
    const int s = blockIdx.y;
    if (g_cnt[s] == 0) return;
    const int p0 = blockIdx.x * TPT;
    const size_t base = ((size_t)s * Pq + p0) * Kq;

    for (int i = tid; i < TPT * Kq; i += 128) {
        int t = i >> 5, k = i & 31;
        s_off[t][k] = (uint32_t)nbr[base + (size_t)t * Kq + k] << 8;   // *256B row
        const float* Lp = lc + (base + (size_t)t * Kq + k) * 3;
        s_L[t][k] = make_ulonglong2(pk2(Lp[0], Lp[1]), pk2(Lp[2], 1.0f));
    }
    __syncthreads();

    const int c8 = tid & 15;          // channel octet: channels 8*c8 .. 8*c8+7
    const int h = tid >> 4;           // 0..7 point group
    const char* ptsb = (const char*)(g_Ph + (size_t)s * Nq * Cq) + 16 * c8;

#pragma unroll 1
    for (int tt = 0; tt < 2; tt++) {
        const int t = tt * 8 + h;
        unsigned long long a01[8], a23[8];
#pragma unroll
        for (int c = 0; c < 8; c++) { a01[c] = 0ull; a23[c] = 0ull; }
#pragma unroll 8
        for (int k = 0; k < Kq; k++) {
            uint4 w = *reinterpret_cast<const uint4*>(ptsb + s_off[t][k]);
            ulonglong2 L = s_L[t][k];
            float2 v0 = __half22float2(h2_from_u32(w.x));
            float2 v1 = __half22float2(h2_from_u32(w.y));
            float2 v2 = __half22float2(h2_from_u32(w.z));
            float2 v3 = __half22float2(h2_from_u32(w.w));
            unsigned long long pv;
            pv = pk2(v0.x, v0.x); fma2(a01[0], pv, L.x); fma2(a23[0], pv, L.y);
            pv = pk2(v0.y, v0.y); fma2(a01[1], pv, L.x); fma2(a23[1], pv, L.y);
            pv = pk2(v1.x, v1.x); fma2(a01[2], pv, L.x); fma2(a23[2], pv, L.y);
            pv = pk2(v1.y, v1.y); fma2(a01[3], pv, L.x); fma2(a23[3], pv, L.y);
            pv = pk2(v2.x, v2.x); fma2(a01[4], pv, L.x); fma2(a23[4], pv, L.y);
            pv = pk2(v2.y, v2.y); fma2(a01[5], pv, L.x); fma2(a23[5], pv, L.y);
            pv = pk2(v3.x, v3.x); fma2(a01[6], pv, L.x); fma2(a23[6], pv, L.y);
            pv = pk2(v3.y, v3.y); fma2(a01[7], pv, L.x); fma2(a23[7], pv, L.y);
        }
        const size_t rb = ((size_t)s * Pq + p0 + t) * 512;
        float2 f01[8], f23[8];
#pragma unroll
        for (int c = 0; c < 8; c++) { f01[c] = up2(a01[c]); f23[c] = up2(a23[c]); }
        uint4 st;
        // d = 0
        st.x = u32_from_h2(__floats2half2_rn(f01[0].x, f01[1].x));
        st.y = u32_from_h2(__floats2half2_rn(f01[2].x, f01[3].x));
        st.z = u32_from_h2(__floats2half2_rn(f01[4].x, f01[5].x));
        st.w = u32_from_h2(__floats2half2_rn(f01[6].x, f01[7].x));
        *reinterpret_cast<uint4*>(g_S + rb + 0 * 128 + 8 * c8) = st;
        // d = 1
        st.x = u32_from_h2(__floats2half2_rn(f01[0].y, f01[1].y));
        st.y = u32_from_h2(__floats2half2_rn(f01[2].y, f01[3].y));
        st.z = u32_from_h2(__floats2half2_rn(f01[4].y, f01[5].y));
        st.w = u32_from_h2(__floats2half2_rn(f01[6].y, f01[7].y));
        *reinterpret_cast<uint4*>(g_S + rb + 1 * 128 + 8 * c8) = st;
        // d = 2
        st.x = u32_from_h2(__floats2half2_rn(f23[0].x, f23[1].x));
        st.y = u32_from_h2(__floats2half2_rn(f23[2].x, f23[3].x));
        st.z = u32_from_h2(__floats2half2_rn(f23[4].x, f23[5].x));
        st.w = u32_from_h2(__floats2half2_rn(f23[6].x, f23[7].x));
        *reinterpret_cast<uint4*>(g_S + rb + 2 * 128 + 8 * c8) = st;
        // d = 3
        st.x = u32_from_h2(__floats2half2_rn(f23[0].y, f23[1].y));
        st.y = u32_from_h2(__floats2half2_rn(f23[2].y, f23[3].y));
        st.z = u32_from_h2(__floats2half2_rn(f23[4].y, f23[5].y));
        st.w = u32_from_h2(__floats2half2_rn(f23[6].y, f23[7].y));
        *reinterpret_cast<uint4*>(g_S + rb + 3 * 128 + 8 * c8) = st;
    }
}

// ============================================================
// GEMM: Y[p,j] = S[p,i] * A'[j,i]^T  via mma.sync fp16
//   block tile 128p x 64j; K chunks of 64 (8 chunks); 2-stage;
//   ONE barrier per chunk; 3 CTAs/SM (R13/R15 config)
// ============================================================
#define STILE_B 18432                // 128 rows * 144B
#define ATILE_B 9216                 // 64 rows * 144B
#define OFF_S   0
#define OFF_A   (STILE_B)
#define BUF_B   (STILE_B + ATILE_B)       // 27648
#define GSM_TOTAL (2 * BUF_B)             // 55296 (epilogue 64*132*4=33792 fits)

__global__ __launch_bounds__(256, 3) void gemm_kernel() {
    extern __shared__ __align__(128) char sm[];
    const int tid = threadIdx.x;
    const int wid = tid >> 5;
    const int L = tid & 31;
    const int srcb = blockIdx.y;
    if (g_cnt[srcb] == 0) return;
    const int pt = blockIdx.x >> 1;
    const int jh = blockIdx.x & 1;     // which 64-j half
    const int wm = wid >> 1;           // 0..3  (p dim, 32 each)
    const int wn = wid & 1;            // 0..1  (j dim, 32 each)

    const uint32_t smb = smem_to_u32(sm);
    const __half* Sp = g_S + ((size_t)srcb * Pq + pt * 128) * 512;
    const __half* Ah = g_Ahf + (size_t)(jh * 64) * 512;

    float acc[2][4][4];
#pragma unroll
    for (int mt = 0; mt < 2; mt++)
#pragma unroll
        for (int nt = 0; nt < 4; nt++)
#pragma unroll
            for (int q = 0; q < 4; q++) acc[mt][nt][q] = 0.f;

    const int grp = L >> 3, lr = L & 7;
    const uint32_t aRow = (uint32_t)(wm * 32 + (grp & 1) * 8 + lr) * 144
                        + (uint32_t)(grp >> 1) * 16;
    const uint32_t bRow = (uint32_t)(wn * 32 + (grp >> 1) * 8 + lr) * 144
                        + (uint32_t)(grp & 1) * 16;

#define ISSUE(kc, buf) do {                                                     \
        uint32_t bb = smb + (uint32_t)(buf) * BUF_B;                            \
        _Pragma("unroll")                                                       \
        for (int ii = 0; ii < 4; ii++) {                                        \
            int u = tid + ii * 256;                                             \
            int row = u >> 3, seg = u & 7;                                      \
            CP_ASYNC16(bb + OFF_S + (uint32_t)row * 144 + (uint32_t)seg * 16,   \
                       (const char*)(Sp + (size_t)row * 512 + (kc) * 64 + seg * 8)); \
        }                                                                       \
        _Pragma("unroll")                                                       \
        for (int ii = 0; ii < 2; ii++) {                                        \
            int u = tid + ii * 256;                                             \
            int row = u >> 3, seg = u & 7;                                      \
            CP_ASYNC16(bb + OFF_A + (uint32_t)row * 144 + (uint32_t)seg * 16,   \
                       (const char*)(Ah + (size_t)row * 512 + (kc) * 64 + seg * 8)); \
        }                                                                       \
        CP_COMMIT();                                                            \
    } while (0)

    ISSUE(0, 0);

#pragma unroll 1
    for (int kc = 0; kc < 8; kc++) {
        CP_WAIT(0);
        __syncthreads();
        if (kc < 7) ISSUE(kc + 1, (kc + 1) & 1);   // safe: readers passed sync

        const uint32_t bb = smb + (uint32_t)(kc & 1) * BUF_B;
#pragma unroll
        for (int ks = 0; ks < 4; ks++) {
            uint32_t af[2][4];
#pragma unroll
            for (int mt = 0; mt < 2; mt++) {
                uint32_t ao = aRow + (uint32_t)mt * (16 * 144) + (uint32_t)ks * 32;
                ldsm_x4(bb + OFF_S + ao, af[mt]);
            }
#pragma unroll
            for (int ng = 0; ng < 2; ng++) {
                uint32_t bh[4];
                uint32_t bo = bRow + (uint32_t)ng * (16 * 144) + (uint32_t)ks * 32;
                ldsm_x4(bb + OFF_A + bo, bh);
#pragma unroll
                for (int mt = 0; mt < 2; mt++) {
#pragma unroll
                    for (int t2 = 0; t2 < 2; t2++) {
                        mma_f16(acc[mt][2 * ng + t2], af[mt],
                                bh[2 * t2], bh[2 * t2 + 1]);
                    }
                }
            }
        }
    }
    __syncthreads();

    // ---- epilogue: C frags -> smem [64j][132] -> coalesced fp16 Y + LN partials ----
    float* yt = (float*)sm;
    {
        const int pb = wm * 32 + (L >> 2);
        const int jb = wn * 32 + ((L & 3) << 1);
#pragma unroll
        for (int mt = 0; mt < 2; mt++) {
#pragma unroll
            for (int nt = 0; nt < 4; nt++) {
                const float* c = acc[mt][nt];
                int p = pb + mt * 16;
                int j = jb + nt * 8;
                yt[j * 132 + p] = c[0];
                yt[(j + 1) * 132 + p] = c[1];
                yt[j * 132 + p + 8] = c[2];
                yt[(j + 1) * 132 + p + 8] = c[3];
            }
        }
    }
    __syncthreads();

    const int blk2 = srcb * NPTILE + pt;
#pragma unroll 1
    for (int rr = 0; rr < 8; rr++) {
        int j = wid * 8 + rr;          // local j in [0,64)
        int jg = jh * 64 + j;          // global output channel
        float4 v = *reinterpret_cast<const float4*>(yt + j * 132 + L * 4);
        __half2 h0 = __floats2half2_rn(v.x, v.y);
        __half2 h1 = __floats2half2_rn(v.z, v.w);
        uint2 st;
        st.x = *reinterpret_cast<uint32_t*>(&h0);
        st.y = *reinterpret_cast<uint32_t*>(&h1);
        *reinterpret_cast<uint2*>(
            g_Yth + ((size_t)srcb * Cq + jg) * Pq + pt * 128 + L * 4) = st;
        float ls = (v.x + v.y) + (v.z + v.w);
        float lq = (v.x * v.x + v.y * v.y) + (v.z * v.z + v.w * v.w);
#pragma unroll
        for (int o = 16; o > 0; o >>= 1) {
            ls += __shfl_xor_sync(0xFFFFFFFFu, ls, o);
            lq += __shfl_xor_sync(0xFFFFFFFFu, lq, o);
        }
        if (L == 0) {
            g_ps[(size_t)blk2 * Cq + jg] = ls;
            g_pq[(size_t)blk2 * Cq + jg] = lq;
        }
    }
}

// ============================================================
// out: 256 blocks (j x b-half). Each block reduces LN stats for its
//   channel ONCE (warp shuffles, fixed order -> deterministic), then
//   copies FOUR batch rows (scale/shift/relu) — amortizes the scattered
//   partial-read latency that bound the 1024-block version.
// ============================================================
__global__ __launch_bounds__(256) void out_kernel(float* __restrict__ out,
                                                  const int* __restrict__ didx,
                                                  const float* __restrict__ gamma,
                                                  const float* __restrict__ beta) {
    __shared__ float red_s[8], red_q[8];
    const int tid = threadIdx.x;
    const int j = blockIdx.x >> 1;        // channel
    const int bh = blockIdx.x & 1;        // batch half: b = bh*4 .. bh*4+3

    // weighted partial for row tid; warp-reduce; 8 warp sums; broadcast sum
    {
        float w = (float)g_cnt[tid >> 5];
        float s = w * g_ps[(size_t)tid * Cq + j];
        float q = w * g_pq[(size_t)tid * Cq + j];
#pragma unroll
        for (int o = 16; o > 0; o >>= 1) {
            s += __shfl_xor_sync(0xFFFFFFFFu, s, o);
            q += __shfl_xor_sync(0xFFFFFFFFu, q, o);
        }
        if ((tid & 31) == 0) {
            red_s[tid >> 5] = s;
            red_q[tid >> 5] = q;
        }
    }
    __syncthreads();
    float S = ((red_s[0] + red_s[1]) + (red_s[2] + red_s[3]))
            + ((red_s[4] + red_s[5]) + (red_s[6] + red_s[7]));
    float Q = ((red_q[0] + red_q[1]) + (red_q[2] + red_q[3]))
            + ((red_q[4] + red_q[5]) + (red_q[6] + red_q[7]));
    const float inv = 1.0f / (float)(Bq * Pq);
    const float mean = S * inv;
    const float var = Q * inv - mean * mean;
    const float sc = rsqrtf(var + EPSq) * gamma[j];
    const float sh = beta[j] - mean * sc;

#pragma unroll 1
    for (int r = 0; r < 4; r++) {
        const int b = bh * 4 + r;
        const int src = didx[b];
        const uint4* in = reinterpret_cast<const uint4*>(
            g_Yth + ((size_t)src * Cq + j) * Pq);
        float4* op = reinterpret_cast<float4*>(out + ((size_t)b * Cq + j) * Pq);
#pragma unroll
        for (int k = 0; k < 2; k++) {
            int idx = tid + k * 256;          // 512 uint4 per row
            uint4 v = in[idx];
            float2 a0 = __half22float2(h2_from_u32(v.x));
            float2 a1 = __half22float2(h2_from_u32(v.y));
            float2 a2 = __half22float2(h2_from_u32(v.z));
            float2 a3 = __half22float2(h2_from_u32(v.w));
            float4 o0, o1;
            o0.x = fmaxf(fmaf(a0.x, sc, sh), 0.f);
            o0.y = fmaxf(fmaf(a0.y, sc, sh), 0.f);
            o0.z = fmaxf(fmaf(a1.x, sc, sh), 0.f);
            o0.w = fmaxf(fmaf(a1.y, sc, sh), 0.f);
            o1.x = fmaxf(fmaf(a2.x, sc, sh), 0.f);
            o1.y = fmaxf(fmaf(a2.y, sc, sh), 0.f);
            o1.z = fmaxf(fmaf(a3.x, sc, sh), 0.f);
            o1.w = fmaxf(fmaf(a3.y, sc, sh), 0.f);
            op[idx * 2] = o0;
            op[idx * 2 + 1] = o1;
        }
    }
}

// ============================================================
// Launch
// ============================================================
extern "C" void kernel_launch(void* const* d_in, const int* in_sizes, int n_in,
                              void* d_out, int out_size) {
    const float* xyz    = (const float*)d_in[0];
    const float* points = (const float*)d_in[1];
    const float* lc     = (const float*)d_in[2];
    const int*   nbr    = (const int*)d_in[3];
    const int*   didx   = (const int*)d_in[4];
    const float* Ww     = (const float*)d_in[5];
    const float* bw     = (const float*)d_in[6];
    const float* Wl     = (const float*)d_in[7];
    const float* gamma  = (const float*)d_in[9];
    const float* beta   = (const float*)d_in[10];
    float* out = (float*)d_out;

    cudaMemcpyAsync(out, xyz, (size_t)Bq * Pq * 3 * sizeof(float),
                    cudaMemcpyDeviceToDevice, 0);

    cudaFuncSetAttribute(gemm_kernel,
                         cudaFuncAttributeMaxDynamicSharedMemorySize, GSM_TOTAL);

    prepconv_kernel<<<CONV_BLKS + 256, 256>>>(points, Ww, bw, Wl, didx);

    dim3 gg(GBLK_PER_B, Bq);
    gather_kernel<<<gg, 128>>>(lc, nbr);

    dim3 g2(NPTILE * 2, Bq);
    gemm_kernel<<<g2, 256, GSM_TOTAL>>>();

    out_kernel<<<2 * Cq, 256>>>(out + (size_t)Bq * Pq * 3, didx, gamma, beta);
}